// round 4
// baseline (speedup 1.0000x reference)
#include <cuda_runtime.h>
#include <cuda_bf16.h>

// y[n] = tanh(W[t_n] @ x[n] + b[t_n]);  N=131072, D=64, 256 types (int32).
// Pipeline: atomic-free counting sort by type (block hists -> single-block
// scan -> smem-atomic scatter), then per (type, 128-atom tile) CTA:
// W[t] + all 128 x rows staged to smem ONCE (2 barriers total), W row in
// registers, broadcast-LDS x, FFMA inner loop, tanh, coalesced store.

#define D 64
#define MAX_N 131072
#define TILE 128
#define MAX_TILES 8          // covers up to 1024 atoms/type (mean 512)
#define G 128                // sort blocks
#define WPITCH 68            // smem W pitch (floats); 16B-aligned, conflict-light

__device__ int g_off[257];          // per-type global offsets
__device__ int g_bhist[256 * G];    // [type][block] counts
__device__ int g_bbase[256 * G];    // [type][block] scatter bases
__device__ int g_perm[MAX_N];

// ---- 1. per-block histogram ----
__global__ void k_hist(const int* __restrict__ types, int n)
{
    __shared__ int sh[256];
    const int g = blockIdx.x;
    sh[threadIdx.x] = 0;
    __syncthreads();
    const int chunk = (n + G - 1) / G;
    const int lo = g * chunk, hi = min(n, lo + chunk);
    for (int i = lo + threadIdx.x; i < hi; i += blockDim.x)
        atomicAdd(&sh[types[i] & 255], 1);
    __syncthreads();
    g_bhist[threadIdx.x * G + g] = sh[threadIdx.x];
}

// ---- 2. single-block scan: type offsets + per-(type,block) bases ----
__global__ void k_scan(int n)
{
    __shared__ int s[256];
    const int t = threadIdx.x;
    int sum = 0;
#pragma unroll 4
    for (int g = 0; g < G; g++) sum += g_bhist[t * G + g];
    s[t] = sum;
    __syncthreads();
    for (int d = 1; d < 256; d <<= 1) {
        int add = (t >= d) ? s[t - d] : 0;
        __syncthreads();
        s[t] += add;
        __syncthreads();
    }
    const int tbase = s[t] - sum;      // exclusive type offset
    g_off[t] = tbase;
    if (t == 255) g_off[256] = n;
    int run = tbase;
    for (int g = 0; g < G; g++) {
        g_bbase[t * G + g] = run;
        run += g_bhist[t * G + g];
    }
}

// ---- 3. scatter with smem counters (no global atomics) ----
__global__ void k_scatter(const int* __restrict__ types, int n)
{
    __shared__ int cnt[256];
    const int g = blockIdx.x;
    cnt[threadIdx.x] = g_bbase[threadIdx.x * G + g];
    __syncthreads();
    const int chunk = (n + G - 1) / G;
    const int lo = g * chunk, hi = min(n, lo + chunk);
    for (int i = lo + threadIdx.x; i < hi; i += blockDim.x) {
        int t = types[i] & 255;
        int dst = atomicAdd(&cnt[t], 1);   // smem atomic: ~2 cyc/lane
        g_perm[dst] = i;
    }
}

// ---- 4. compute ----
__global__ __launch_bounds__(256, 2)
void k_compute(const float* __restrict__ x,
               const float* __restrict__ W,
               const float* __restrict__ b,
               float* __restrict__ out)
{
    const int t    = blockIdx.x;
    const int tile = blockIdx.y;
    const int base = g_off[t] + tile * TILE;
    const int end  = g_off[t + 1];
    if (base >= end) return;

    __shared__ float sW[D * WPITCH];       // ~17 KB
    __shared__ float xs[TILE][D];          // 32 KB
    __shared__ int   sp[TILE];

    const int tid = threadIdx.x;
    const int s   = tid >> 6;              // slot 0..3 -> rows s*32..s*32+31
    const int o   = tid & 63;

    // Stage W[t] (16 KB) coalesced.
    const float4* Wt4 = reinterpret_cast<const float4*>(W + (size_t)t * D * D);
#pragma unroll
    for (int i = 0; i < 4; i++) {
        int g4  = tid + i * 256;
        float4 v = Wt4[g4];
        *reinterpret_cast<float4*>(&sW[(g4 >> 4) * WPITCH + (g4 & 15) * 4]) = v;
    }
    // Stage perm slice.
    if (tid < TILE)
        sp[tid] = (base + tid < end) ? g_perm[base + tid] : -1;
    __syncthreads();

    // Stage all 128 x rows (gathered, each row a coalesced 256B load).
#pragma unroll
    for (int i = 0; i < 8; i++) {
        int idx = tid + i * 256;           // 0..2047 float4 slots
        int row = idx >> 4, c4 = idx & 15;
        int a = sp[row];
        if (a >= 0)
            reinterpret_cast<float4*>(xs[row])[c4] =
                reinterpret_cast<const float4*>(x + (size_t)a * D)[c4];
    }
    __syncthreads();

    // Thread-private W row.
    float4 lw[16];
#pragma unroll
    for (int i = 0; i < 16; i++)
        lw[i] = *reinterpret_cast<const float4*>(&sW[o * WPITCH + i * 4]);
    const float bias = b[(size_t)t * D + o];

    // 32 atoms per slot, no further barriers.
#pragma unroll 4
    for (int j = 0; j < 32; j++) {
        const int r = s * 32 + j;
        const int a = sp[r];
        if (a < 0) continue;
        const float4* xv = reinterpret_cast<const float4*>(xs[r]);  // broadcast
        float acc0 = bias, acc1 = 0.f, acc2 = 0.f, acc3 = 0.f;
#pragma unroll
        for (int i = 0; i < 16; i += 2) {
            float4 w0 = lw[i], w1 = lw[i + 1];
            float4 x0 = xv[i], x1 = xv[i + 1];
            acc0 = fmaf(w0.x, x0.x, acc0);
            acc1 = fmaf(w0.y, x0.y, acc1);
            acc2 = fmaf(w0.z, x0.z, acc2);
            acc3 = fmaf(w0.w, x0.w, acc3);
            acc0 = fmaf(w1.x, x1.x, acc0);
            acc1 = fmaf(w1.y, x1.y, acc1);
            acc2 = fmaf(w1.z, x1.z, acc2);
            acc3 = fmaf(w1.w, x1.w, acc3);
        }
        out[(size_t)a * D + o] = tanhf((acc0 + acc1) + (acc2 + acc3));
    }
}

// ---- launch ----
extern "C" void kernel_launch(void* const* d_in, const int* in_sizes, int n_in,
                              void* d_out, int out_size)
{
    const float* x   = (const float*)d_in[0];
    const int*   ty  = (const int*)d_in[1];
    const float* W   = (const float*)d_in[2];
    const float* b   = (const float*)d_in[3];
    float*       out = (float*)d_out;

    const int n = in_sizes[0] / D;

    k_hist<<<G, 256>>>(ty, n);
    k_scan<<<1, 256>>>(n);
    k_scatter<<<G, 256>>>(ty, n);
    dim3 grid(256, MAX_TILES);
    k_compute<<<grid, 256>>>(x, W, b, out);
}

// round 7
// speedup vs baseline: 3.1493x; 3.1493x over previous
#include <cuda_runtime.h>
#include <cuda_bf16.h>
#include <cstdint>

// y[n] = tanh(W[t_n] @ x[n] + b[t_n]);  N=131072, D=64, 256 types (int32).
// 1) counting sort by type (atomic-free, two-level)
// 2) per (type, 128-atom tile) CTA: HMMA bf16 GEMM (mma.sync m16n8k16) with
//    split-bf16 (hi+lo, 3 chained MMAs) -> ~1e-5 GEMM error, then
//    bias + tanh.approx epilogue.  (tcgen05 unavailable: harness builds via
//    compute_103 virtual arch which rejects sm_103a-only features.)

#define D 64
#define MAX_N 131072
#define TILE 128
#define MAX_TILES 8
#define G 128
#define XPB 144            // smem row pitch in bytes (72 bf16); 144%128==16 -> conflict-free

__device__ int g_off[257];
__device__ int g_bhist[G * 256];   // [g][t]  (transposed for coalesced scan)
__device__ int g_bbase[256 * G];   // [t][g]
__device__ int g_perm[MAX_N];

// ------------------------------------------------------------------ sort ----
__global__ void k_hist(const int* __restrict__ types, int n)
{
    __shared__ int sh[256];
    const int g = blockIdx.x;
    sh[threadIdx.x] = 0;
    __syncthreads();
    const int chunk = (n + G - 1) / G;
    const int lo = g * chunk, hi = min(n, lo + chunk);
    for (int i = lo + threadIdx.x; i < hi; i += blockDim.x)
        atomicAdd(&sh[types[i] & 255], 1);
    __syncthreads();
    g_bhist[g * 256 + threadIdx.x] = sh[threadIdx.x];
}

__global__ void k_scan(int n)   // 1 block: per-type exclusive offsets
{
    __shared__ int s[256];
    const int t = threadIdx.x;
    int sum = 0;
#pragma unroll 8
    for (int g = 0; g < G; g++) sum += g_bhist[g * 256 + t];   // coalesced
    s[t] = sum;
    __syncthreads();
    for (int d = 1; d < 256; d <<= 1) {
        int add = (t >= d) ? s[t - d] : 0;
        __syncthreads();
        s[t] += add;
        __syncthreads();
    }
    g_off[t] = s[t] - sum;
    if (t == 255) g_off[256] = n;
}

__global__ void k_scan2()       // grid=256 (type), threads=G: per-block bases
{
    __shared__ int s[G];
    const int t = blockIdx.x, g = threadIdx.x;
    const int v = g_bhist[g * 256 + t];
    s[g] = v;
    __syncthreads();
    for (int d = 1; d < G; d <<= 1) {
        int add = (g >= d) ? s[g - d] : 0;
        __syncthreads();
        s[g] += add;
        __syncthreads();
    }
    g_bbase[t * G + g] = g_off[t] + s[g] - v;
}

__global__ void k_scatter(const int* __restrict__ types, int n)
{
    __shared__ int cnt[256];
    const int g = blockIdx.x;
    cnt[threadIdx.x] = g_bbase[threadIdx.x * G + g];
    __syncthreads();
    const int chunk = (n + G - 1) / G;
    const int lo = g * chunk, hi = min(n, lo + chunk);
    for (int i = lo + threadIdx.x; i < hi; i += blockDim.x) {
        int t = types[i] & 255;
        int dst = atomicAdd(&cnt[t], 1);
        g_perm[dst] = i;
    }
}

// --------------------------------------------------------------- helpers ----
__device__ __forceinline__ uint32_t smem_u32(const void* p) {
    uint32_t a;
    asm("{ .reg .u64 t; cvta.to.shared.u64 t, %1; cvt.u32.u64 %0, t; }"
        : "=r"(a) : "l"(p));
    return a;
}
__device__ __forceinline__ uint32_t lds32(uint32_t a) {
    uint32_t v;
    asm("ld.shared.b32 %0, [%1];" : "=r"(v) : "r"(a));
    return v;
}
__device__ __forceinline__ float tanh_fast(float x) {
    float r;
    asm("tanh.approx.f32 %0, %1;" : "=f"(r) : "f"(x));
    return r;
}
__device__ __forceinline__ void mma16816(float* c, const uint32_t* a,
                                         uint32_t b0, uint32_t b1)
{
    asm volatile(
        "mma.sync.aligned.m16n8k16.row.col.f32.bf16.bf16.f32 "
        "{%0,%1,%2,%3}, {%4,%5,%6,%7}, {%8,%9}, {%0,%1,%2,%3};"
        : "+f"(c[0]), "+f"(c[1]), "+f"(c[2]), "+f"(c[3])
        : "r"(a[0]), "r"(a[1]), "r"(a[2]), "r"(a[3]), "r"(b0), "r"(b1));
}
__device__ __forceinline__ void cvt_split(float4 v, uint2& hi, uint2& lo)
{
    __nv_bfloat162 h01 = __floats2bfloat162_rn(v.x, v.y);
    __nv_bfloat162 h23 = __floats2bfloat162_rn(v.z, v.w);
    __nv_bfloat162 l01 = __floats2bfloat162_rn(
        v.x - __bfloat162float(h01.x), v.y - __bfloat162float(h01.y));
    __nv_bfloat162 l23 = __floats2bfloat162_rn(
        v.z - __bfloat162float(h23.x), v.w - __bfloat162float(h23.y));
    hi = make_uint2(*(uint32_t*)&h01, *(uint32_t*)&h23);
    lo = make_uint2(*(uint32_t*)&l01, *(uint32_t*)&l23);
}

// ------------------------------------------------------------- compute ----
// dynamic smem layout (bytes)
#define SM_SP    0                       // 128 ints
#define SM_BIAS  512                     // 64 floats
#define SM_XHI   768                     // 128*144
#define SM_XLO   (SM_XHI + TILE * XPB)   // 19200
#define SM_WHI   (SM_XLO + TILE * XPB)   // 37632
#define SM_WLO   (SM_WHI + 64 * XPB)     // 46848
#define SM_TOTAL (SM_WLO + 64 * XPB)     // 56064
#define DXL      (SM_XLO - SM_XHI)
#define DWL      (SM_WLO - SM_WHI)

__global__ __launch_bounds__(128)
void k_compute(const float* __restrict__ x,
               const float* __restrict__ W,
               const float* __restrict__ b,
               float* __restrict__ out)
{
    extern __shared__ char smem[];
    const int t    = blockIdx.x;
    const int tile = blockIdx.y;
    const int base = g_off[t] + tile * TILE;
    const int end  = g_off[t + 1];
    if (base >= end) return;

    const int tid = threadIdx.x;
    int*   sp    = (int*)(smem + SM_SP);
    float* sbias = (float*)(smem + SM_BIAS);

    if (tid < TILE) sp[tid] = (base + tid < end) ? g_perm[base + tid] : -1;
    if (tid < 64)   sbias[tid] = b[(size_t)t * 64 + tid];
    __syncthreads();

    // Stage X tile: fp32 -> bf16 hi+lo, row pitch 144B.
#pragma unroll
    for (int i = 0; i < 16; i++) {
        int idx = tid + i * 128;           // 0..2047 float4 slots
        int row = idx >> 4, c4 = idx & 15;
        int a = sp[row];
        if (a >= 0) {
            float4 v = reinterpret_cast<const float4*>(x + (size_t)a * D)[c4];
            uint2 hi, lo;
            cvt_split(v, hi, lo);
            char* p = smem + SM_XHI + row * XPB + c4 * 8;
            *(uint2*)p         = hi;
            *(uint2*)(p + DXL) = lo;
        }
    }
    // Stage W[t] (64x64): same split.
    const float4* Wt = reinterpret_cast<const float4*>(W + (size_t)t * D * D);
#pragma unroll
    for (int i = 0; i < 8; i++) {
        int idx = tid + i * 128;           // 0..1023
        int row = idx >> 4, c4 = idx & 15;
        uint2 hi, lo;
        cvt_split(Wt[idx], hi, lo);
        char* p = smem + SM_WHI + row * XPB + c4 * 8;
        *(uint2*)p         = hi;
        *(uint2*)(p + DWL) = lo;
    }
    __syncthreads();

    const int wid = tid >> 5, lane = tid & 31;
    const int gq = lane >> 2, tig = lane & 3;
    const uint32_t sb = smem_u32(smem);
    const uint32_t aBase = sb + SM_XHI + (wid * 32 + gq) * XPB + tig * 4;
    const uint32_t bBase = sb + SM_WHI + gq * XPB + tig * 4;

    float acc[2][8][4];
#pragma unroll
    for (int mt = 0; mt < 2; mt++)
#pragma unroll
        for (int nt = 0; nt < 8; nt++)
#pragma unroll
            for (int r = 0; r < 4; r++) acc[mt][nt][r] = 0.f;

#pragma unroll
    for (int k = 0; k < 4; k++) {
        uint32_t ah[2][4], al[2][4];
#pragma unroll
        for (int mt = 0; mt < 2; mt++) {
            uint32_t pa = aBase + mt * (16 * XPB) + k * 32;
            ah[mt][0] = lds32(pa);
            ah[mt][1] = lds32(pa + 8 * XPB);
            ah[mt][2] = lds32(pa + 16);
            ah[mt][3] = lds32(pa + 8 * XPB + 16);
            al[mt][0] = lds32(pa + DXL);
            al[mt][1] = lds32(pa + DXL + 8 * XPB);
            al[mt][2] = lds32(pa + DXL + 16);
            al[mt][3] = lds32(pa + DXL + 8 * XPB + 16);
        }
#pragma unroll
        for (int nt = 0; nt < 8; nt++) {
            uint32_t pb = bBase + nt * (8 * XPB) + k * 32;
            uint32_t bh0 = lds32(pb),       bh1 = lds32(pb + 16);
            uint32_t bl0 = lds32(pb + DWL), bl1 = lds32(pb + DWL + 16);
#pragma unroll
            for (int mt = 0; mt < 2; mt++) {
                mma16816(acc[mt][nt], ah[mt], bh0, bh1);  // hi*hi
                mma16816(acc[mt][nt], al[mt], bh0, bh1);  // lo*hi
                mma16816(acc[mt][nt], ah[mt], bl0, bl1);  // hi*lo
            }
        }
    }

    // Epilogue: bias + tanh, write gathered rows.
    float br[16];
#pragma unroll
    for (int nt = 0; nt < 8; nt++) {
        br[2 * nt]     = sbias[8 * nt + 2 * tig];
        br[2 * nt + 1] = sbias[8 * nt + 2 * tig + 1];
    }
#pragma unroll
    for (int mt = 0; mt < 2; mt++) {
#pragma unroll
        for (int h = 0; h < 2; h++) {
            const int r = wid * 32 + mt * 16 + h * 8 + gq;
            const int a = sp[r];
            if (a < 0) continue;
            float* orow = out + (size_t)a * D;
#pragma unroll
            for (int nt = 0; nt < 8; nt++) {
                float2 y;
                y.x = tanh_fast(acc[mt][nt][2 * h]     + br[2 * nt]);
                y.y = tanh_fast(acc[mt][nt][2 * h + 1] + br[2 * nt + 1]);
                *(float2*)(orow + 8 * nt + 2 * tig) = y;
            }
        }
    }
}

// -------------------------------------------------------------- launch ----
extern "C" void kernel_launch(void* const* d_in, const int* in_sizes, int n_in,
                              void* d_out, int out_size)
{
    const float* x   = (const float*)d_in[0];
    const int*   ty  = (const int*)d_in[1];
    const float* W   = (const float*)d_in[2];
    const float* b   = (const float*)d_in[3];
    float*       out = (float*)d_out;

    const int n = in_sizes[0] / D;

    cudaFuncSetAttribute(k_compute,
                         cudaFuncAttributeMaxDynamicSharedMemorySize, SM_TOTAL);

    k_hist<<<G, 256>>>(ty, n);
    k_scan<<<1, 256>>>(n);
    k_scan2<<<256, G>>>();
    k_scatter<<<G, 256>>>(ty, n);
    dim3 grid(256, MAX_TILES);
    k_compute<<<grid, 128, SM_TOTAL>>>(x, W, b, out);
}

// round 8
// speedup vs baseline: 3.6913x; 1.1721x over previous
#include <cuda_runtime.h>
#include <cuda_bf16.h>
#include <cstdint>

// y[n] = tanh(W[t_n] @ x[n] + b[t_n]);  N=131072, D=64, 256 types (int32).
// 1) wide atomic-free counting sort:
//      k_hist (512x256, 1 elem/thr) -> k_scan2 (per-type block-prefix + totals)
//      -> k_scan (type offsets) -> k_scatter (512x256, smem counters)
// 2) per (type, 128-atom tile) CTA, 256 threads: HMMA bf16 m16n8k16 GEMM,
//    split-bf16 (hi+lo, 3 chained MMAs), ldmatrix fragment loads,
//    bias + tanh.approx epilogue.

#define D 64
#define MAX_N 131072
#define TILE 128
#define MAX_TILES 8
#define G 512
#define XPB 144   // smem row pitch bytes; 144%128==16 -> ldmatrix conflict-free

__device__ int g_off[257];
__device__ int g_bhist[G * 256];    // [g][t]
__device__ int g_lbase[256 * G];    // [t][g]  local (within-type) block bases
__device__ int g_tot[256];          // per-type totals
__device__ int g_perm[MAX_N];

// ------------------------------------------------------------------ sort ----
__global__ void k_hist(const int* __restrict__ types, int n)
{
    __shared__ int sh[256];
    const int g = blockIdx.x;
    sh[threadIdx.x] = 0;
    __syncthreads();
    const int chunk = (n + G - 1) / G;
    const int lo = g * chunk, hi = min(n, lo + chunk);
    for (int i = lo + threadIdx.x; i < hi; i += blockDim.x)
        atomicAdd(&sh[types[i] & 255], 1);
    __syncthreads();
    g_bhist[g * 256 + threadIdx.x] = sh[threadIdx.x];
}

__global__ void k_scan2()   // grid=256 (type t), G threads: prefix over blocks
{
    __shared__ int s[G];
    const int t = blockIdx.x, g = threadIdx.x;
    const int v = g_bhist[g * 256 + t];
    s[g] = v;
    __syncthreads();
    for (int d = 1; d < G; d <<= 1) {
        int add = (g >= d) ? s[g - d] : 0;
        __syncthreads();
        s[g] += add;
        __syncthreads();
    }
    g_lbase[t * G + g] = s[g] - v;       // exclusive, local to type
    if (g == G - 1) g_tot[t] = s[g];
}

__global__ void k_scan(int n)   // 1 block: scan totals -> type offsets
{
    __shared__ int s[256];
    const int t = threadIdx.x;
    const int v = g_tot[t];
    s[t] = v;
    __syncthreads();
    for (int d = 1; d < 256; d <<= 1) {
        int add = (t >= d) ? s[t - d] : 0;
        __syncthreads();
        s[t] += add;
        __syncthreads();
    }
    g_off[t] = s[t] - v;
    if (t == 255) g_off[256] = n;
}

__global__ void k_scatter(const int* __restrict__ types, int n)
{
    __shared__ int cnt[256];
    const int g = blockIdx.x;
    cnt[threadIdx.x] = g_off[threadIdx.x] + g_lbase[threadIdx.x * G + g];
    __syncthreads();
    const int chunk = (n + G - 1) / G;
    const int lo = g * chunk, hi = min(n, lo + chunk);
    for (int i = lo + threadIdx.x; i < hi; i += blockDim.x) {
        int t = types[i] & 255;
        int dst = atomicAdd(&cnt[t], 1);
        g_perm[dst] = i;
    }
}

// --------------------------------------------------------------- helpers ----
__device__ __forceinline__ uint32_t smem_u32(const void* p) {
    uint32_t a;
    asm("{ .reg .u64 t; cvta.to.shared.u64 t, %1; cvt.u32.u64 %0, t; }"
        : "=r"(a) : "l"(p));
    return a;
}
__device__ __forceinline__ float tanh_fast(float x) {
    float r;
    asm("tanh.approx.f32 %0, %1;" : "=f"(r) : "f"(x));
    return r;
}
__device__ __forceinline__ void ldsm4(uint32_t* r, uint32_t addr) {
    asm volatile("ldmatrix.sync.aligned.m8n8.x4.shared.b16 {%0,%1,%2,%3}, [%4];"
                 : "=r"(r[0]), "=r"(r[1]), "=r"(r[2]), "=r"(r[3]) : "r"(addr));
}
__device__ __forceinline__ void mma16816(float* c, const uint32_t* a,
                                         uint32_t b0, uint32_t b1)
{
    asm volatile(
        "mma.sync.aligned.m16n8k16.row.col.f32.bf16.bf16.f32 "
        "{%0,%1,%2,%3}, {%4,%5,%6,%7}, {%8,%9}, {%0,%1,%2,%3};"
        : "+f"(c[0]), "+f"(c[1]), "+f"(c[2]), "+f"(c[3])
        : "r"(a[0]), "r"(a[1]), "r"(a[2]), "r"(a[3]), "r"(b0), "r"(b1));
}
__device__ __forceinline__ void cvt_split(float4 v, uint2& hi, uint2& lo)
{
    __nv_bfloat162 h01 = __floats2bfloat162_rn(v.x, v.y);
    __nv_bfloat162 h23 = __floats2bfloat162_rn(v.z, v.w);
    __nv_bfloat162 l01 = __floats2bfloat162_rn(
        v.x - __bfloat162float(h01.x), v.y - __bfloat162float(h01.y));
    __nv_bfloat162 l23 = __floats2bfloat162_rn(
        v.z - __bfloat162float(h23.x), v.w - __bfloat162float(h23.y));
    hi = make_uint2(*(uint32_t*)&h01, *(uint32_t*)&h23);
    lo = make_uint2(*(uint32_t*)&l01, *(uint32_t*)&l23);
}

// ------------------------------------------------------------- compute ----
#define SM_SP    0
#define SM_BIAS  512
#define SM_XHI   768
#define SM_XLO   (SM_XHI + TILE * XPB)
#define SM_WHI   (SM_XLO + TILE * XPB)
#define SM_WLO   (SM_WHI + 64 * XPB)
#define SM_TOTAL (SM_WLO + 64 * XPB)     // 56064 bytes
#define DXL      (SM_XLO - SM_XHI)
#define DWL      (SM_WLO - SM_WHI)

__global__ __launch_bounds__(256)
void k_compute(const float* __restrict__ x,
               const float* __restrict__ W,
               const float* __restrict__ b,
               float* __restrict__ out)
{
    extern __shared__ char smem[];
    const int t    = blockIdx.x;
    const int tile = blockIdx.y;
    const int base = g_off[t] + tile * TILE;
    const int end  = g_off[t + 1];
    if (base >= end) return;

    const int tid = threadIdx.x;
    int*   sp    = (int*)(smem + SM_SP);
    float* sbias = (float*)(smem + SM_BIAS);

    if (tid < TILE) sp[tid] = (base + tid < end) ? g_perm[base + tid] : -1;
    if (tid >= 192) sbias[tid - 192] = b[(size_t)t * 64 + (tid - 192)];
    __syncthreads();

    // Stage X tile (fp32 -> bf16 hi+lo), pitch 144B.
#pragma unroll
    for (int i = 0; i < 8; i++) {
        int idx = tid + i * 256;           // 0..2047 float4 slots
        int row = idx >> 4, c4 = idx & 15;
        int a = sp[row];
        if (a >= 0) {
            float4 v = reinterpret_cast<const float4*>(x + (size_t)a * D)[c4];
            uint2 hi, lo;
            cvt_split(v, hi, lo);
            char* p = smem + SM_XHI + row * XPB + c4 * 8;
            *(uint2*)p         = hi;
            *(uint2*)(p + DXL) = lo;
        }
    }
    // Stage W[t] (64x64) split.
    const float4* Wt = reinterpret_cast<const float4*>(W + (size_t)t * D * D);
#pragma unroll
    for (int i = 0; i < 4; i++) {
        int idx = tid + i * 256;           // 0..1023
        int row = idx >> 4, c4 = idx & 15;
        uint2 hi, lo;
        cvt_split(Wt[idx], hi, lo);
        char* p = smem + SM_WHI + row * XPB + c4 * 8;
        *(uint2*)p         = hi;
        *(uint2*)(p + DWL) = lo;
    }
    __syncthreads();

    const int wid = tid >> 5, lane = tid & 31;
    const int gq = lane >> 2, tig = lane & 3;
    const uint32_t sb = smem_u32(smem);

    // ldmatrix lane addresses.
    // A (m16k16): lanes 0-7 rows 0-7 k0 | 8-15 rows 8-15 k0 | 16-23 rows 0-7 k8 | 24-31 rows 8-15 k8
    const uint32_t aAddr = sb + SM_XHI +
        (wid * 16 + (lane & 7) + ((lane >> 3) & 1) * 8) * XPB +
        ((lane >> 4) & 1) * 16;
    // B (two n8k16 tiles): lanes 0-7 rows n0-7 k0 | 8-15 rows n0-7 k8 | 16-23 rows n8-15 k0 | 24-31 rows n8-15 k8
    const uint32_t bAddr = sb + SM_WHI +
        ((lane & 7) + ((lane >> 4) & 1) * 8) * XPB +
        ((lane >> 3) & 1) * 16;

    float acc[8][4];
#pragma unroll
    for (int nt = 0; nt < 8; nt++)
#pragma unroll
        for (int r = 0; r < 4; r++) acc[nt][r] = 0.f;

#pragma unroll
    for (int k = 0; k < 4; k++) {
        uint32_t ah[4], al[4];
        ldsm4(ah, aAddr + k * 32);
        ldsm4(al, aAddr + k * 32 + DXL);
#pragma unroll
        for (int p = 0; p < 4; p++) {      // n-tile pairs: nt = 2p, 2p+1
            uint32_t bh[4], bl[4];
            uint32_t pb = bAddr + p * (16 * XPB) + k * 32;
            ldsm4(bh, pb);
            ldsm4(bl, pb + DWL);
            mma16816(acc[2 * p],     ah, bh[0], bh[1]);
            mma16816(acc[2 * p],     al, bh[0], bh[1]);
            mma16816(acc[2 * p],     ah, bl[0], bl[1]);
            mma16816(acc[2 * p + 1], ah, bh[2], bh[3]);
            mma16816(acc[2 * p + 1], al, bh[2], bh[3]);
            mma16816(acc[2 * p + 1], ah, bl[2], bl[3]);
        }
    }

    // Epilogue: bias + tanh, gathered row writes.
    float br[16];
#pragma unroll
    for (int nt = 0; nt < 8; nt++) {
        br[2 * nt]     = sbias[8 * nt + 2 * tig];
        br[2 * nt + 1] = sbias[8 * nt + 2 * tig + 1];
    }
#pragma unroll
    for (int h = 0; h < 2; h++) {
        const int r = wid * 16 + h * 8 + gq;
        const int a = sp[r];
        if (a < 0) continue;
        float* orow = out + (size_t)a * D;
#pragma unroll
        for (int nt = 0; nt < 8; nt++) {
            float2 y;
            y.x = tanh_fast(acc[nt][2 * h]     + br[2 * nt]);
            y.y = tanh_fast(acc[nt][2 * h + 1] + br[2 * nt + 1]);
            *(float2*)(orow + 8 * nt + 2 * tig) = y;
        }
    }
}

// -------------------------------------------------------------- launch ----
extern "C" void kernel_launch(void* const* d_in, const int* in_sizes, int n_in,
                              void* d_out, int out_size)
{
    const float* x   = (const float*)d_in[0];
    const int*   ty  = (const int*)d_in[1];
    const float* W   = (const float*)d_in[2];
    const float* b   = (const float*)d_in[3];
    float*       out = (float*)d_out;

    const int n = in_sizes[0] / D;

    static bool attr_set = false;
    if (!attr_set) {
        cudaFuncSetAttribute(k_compute,
                             cudaFuncAttributeMaxDynamicSharedMemorySize,
                             SM_TOTAL);
        attr_set = true;
    }

    k_hist<<<G, 256>>>(ty, n);
    k_scan2<<<256, G>>>();
    k_scan<<<1, 256>>>(n);
    k_scatter<<<G, 256>>>(ty, n);
    dim3 grid(256, MAX_TILES);
    k_compute<<<grid, 256, SM_TOTAL>>>(x, W, b, out);
}

// round 9
// speedup vs baseline: 4.2141x; 1.1416x over previous
#include <cuda_runtime.h>
#include <cuda_bf16.h>
#include <cstdint>

// y[n] = tanh(W[t_n] @ x[n] + b[t_n]);  N=131072, D=64, 256 types (int32).
// 1) k_init + k_bucket: single-pass bucketing by type into fixed 1024-slot
//    buckets (block-aggregated global atomics; within-type order is
//    nondeterministic but provably output-invariant).
// 2) k_compute: per (type, 128-atom tile) CTA, 256 threads, HMMA bf16
//    m16n8k16 GEMM with split-bf16 (hi+lo, 3 chained MMAs), ldmatrix
//    fragment loads, bias + tanh.approx epilogue.

#define D 64
#define MAX_N 131072
#define TILE 128
#define CAP 1024          // bucket capacity per type (8 tiles)
#define MAX_TILES (CAP / TILE)
#define BBLK 256          // bucketing blocks
#define XPB 144           // smem row pitch bytes; 144%128==16 -> conflict-free

__device__ int g_cnt[256];            // running bucket cursors
__device__ int g_perm[256 * CAP];     // bucketed atom indices

// ------------------------------------------------------------------ sort ----
__global__ void k_init()
{
    g_cnt[threadIdx.x] = threadIdx.x * CAP;
}

__global__ void k_bucket(const int* __restrict__ types, int n)
{
    __shared__ int sh_cnt[256];
    __shared__ int sh_base[256];
    const int g = blockIdx.x, tid = threadIdx.x;
    sh_cnt[tid] = 0;
    __syncthreads();

    const int chunk = (n + BBLK - 1) / BBLK;          // 512
    const int lo = g * chunk, hi = min(n, lo + chunk);

    int tcache[4];
    int cnt = 0;
    for (int i = lo + tid; i < hi; i += blockDim.x) {
        int t = types[i] & 255;
        tcache[cnt++] = t;
        atomicAdd(&sh_cnt[t], 1);
    }
    __syncthreads();

    const int c = sh_cnt[tid];
    sh_base[tid] = (c > 0) ? atomicAdd(&g_cnt[tid], c) : 0;
    __syncthreads();

    cnt = 0;
    for (int i = lo + tid; i < hi; i += blockDim.x) {
        int t = tcache[cnt++];
        int dst = atomicAdd(&sh_base[t], 1);
        g_perm[dst] = i;
    }
}

// --------------------------------------------------------------- helpers ----
__device__ __forceinline__ uint32_t smem_u32(const void* p) {
    uint32_t a;
    asm("{ .reg .u64 t; cvta.to.shared.u64 t, %1; cvt.u32.u64 %0, t; }"
        : "=r"(a) : "l"(p));
    return a;
}
__device__ __forceinline__ float tanh_fast(float x) {
    float r;
    asm("tanh.approx.f32 %0, %1;" : "=f"(r) : "f"(x));
    return r;
}
__device__ __forceinline__ void ldsm4(uint32_t* r, uint32_t addr) {
    asm volatile("ldmatrix.sync.aligned.m8n8.x4.shared.b16 {%0,%1,%2,%3}, [%4];"
                 : "=r"(r[0]), "=r"(r[1]), "=r"(r[2]), "=r"(r[3]) : "r"(addr));
}
__device__ __forceinline__ void mma16816(float* c, const uint32_t* a,
                                         uint32_t b0, uint32_t b1)
{
    asm volatile(
        "mma.sync.aligned.m16n8k16.row.col.f32.bf16.bf16.f32 "
        "{%0,%1,%2,%3}, {%4,%5,%6,%7}, {%8,%9}, {%0,%1,%2,%3};"
        : "+f"(c[0]), "+f"(c[1]), "+f"(c[2]), "+f"(c[3])
        : "r"(a[0]), "r"(a[1]), "r"(a[2]), "r"(a[3]), "r"(b0), "r"(b1));
}
__device__ __forceinline__ void cvt_split(float4 v, uint2& hi, uint2& lo)
{
    __nv_bfloat162 h01 = __floats2bfloat162_rn(v.x, v.y);
    __nv_bfloat162 h23 = __floats2bfloat162_rn(v.z, v.w);
    __nv_bfloat162 l01 = __floats2bfloat162_rn(
        v.x - __bfloat162float(h01.x), v.y - __bfloat162float(h01.y));
    __nv_bfloat162 l23 = __floats2bfloat162_rn(
        v.z - __bfloat162float(h23.x), v.w - __bfloat162float(h23.y));
    hi = make_uint2(*(uint32_t*)&h01, *(uint32_t*)&h23);
    lo = make_uint2(*(uint32_t*)&l01, *(uint32_t*)&l23);
}

// ------------------------------------------------------------- compute ----
#define SM_SP    0
#define SM_BIAS  512
#define SM_XHI   768
#define SM_XLO   (SM_XHI + TILE * XPB)
#define SM_WHI   (SM_XLO + TILE * XPB)
#define SM_WLO   (SM_WHI + 64 * XPB)
#define SM_TOTAL (SM_WLO + 64 * XPB)     // 56064 bytes
#define DXL      (SM_XLO - SM_XHI)
#define DWL      (SM_WLO - SM_WHI)

__global__ __launch_bounds__(256)
void k_compute(const float* __restrict__ x,
               const float* __restrict__ W,
               const float* __restrict__ b,
               float* __restrict__ out)
{
    extern __shared__ char smem[];
    const int t    = blockIdx.x;
    const int tile = blockIdx.y;
    const int base = t * CAP + tile * TILE;
    const int end  = g_cnt[t];            // t*CAP + count after bucketing
    if (base >= end) return;

    const int tid = threadIdx.x;
    int*   sp    = (int*)(smem + SM_SP);
    float* sbias = (float*)(smem + SM_BIAS);

    if (tid < TILE) sp[tid] = (base + tid < end) ? g_perm[base + tid] : -1;
    if (tid >= 192) sbias[tid - 192] = b[(size_t)t * 64 + (tid - 192)];
    __syncthreads();

    // Stage X tile (fp32 -> bf16 hi+lo), pitch 144B.
#pragma unroll
    for (int i = 0; i < 8; i++) {
        int idx = tid + i * 256;           // 0..2047 float4 slots
        int row = idx >> 4, c4 = idx & 15;
        int a = sp[row];
        if (a >= 0) {
            float4 v = reinterpret_cast<const float4*>(x + (size_t)a * D)[c4];
            uint2 hi, lo;
            cvt_split(v, hi, lo);
            char* p = smem + SM_XHI + row * XPB + c4 * 8;
            *(uint2*)p         = hi;
            *(uint2*)(p + DXL) = lo;
        }
    }
    // Stage W[t] (64x64) split.
    const float4* Wt = reinterpret_cast<const float4*>(W + (size_t)t * D * D);
#pragma unroll
    for (int i = 0; i < 4; i++) {
        int idx = tid + i * 256;           // 0..1023
        int row = idx >> 4, c4 = idx & 15;
        uint2 hi, lo;
        cvt_split(Wt[idx], hi, lo);
        char* p = smem + SM_WHI + row * XPB + c4 * 8;
        *(uint2*)p         = hi;
        *(uint2*)(p + DWL) = lo;
    }
    __syncthreads();

    const int wid = tid >> 5, lane = tid & 31;
    const int gq = lane >> 2, tig = lane & 3;
    const uint32_t sb = smem_u32(smem);

    // ldmatrix lane addresses.
    const uint32_t aAddr = sb + SM_XHI +
        (wid * 16 + (lane & 7) + ((lane >> 3) & 1) * 8) * XPB +
        ((lane >> 4) & 1) * 16;
    const uint32_t bAddr = sb + SM_WHI +
        ((lane & 7) + ((lane >> 4) & 1) * 8) * XPB +
        ((lane >> 3) & 1) * 16;

    float acc[8][4];
#pragma unroll
    for (int nt = 0; nt < 8; nt++)
#pragma unroll
        for (int r = 0; r < 4; r++) acc[nt][r] = 0.f;

#pragma unroll
    for (int k = 0; k < 4; k++) {
        uint32_t ah[4], al[4];
        ldsm4(ah, aAddr + k * 32);
        ldsm4(al, aAddr + k * 32 + DXL);
#pragma unroll
        for (int p = 0; p < 4; p++) {      // n-tile pairs: nt = 2p, 2p+1
            uint32_t bh[4], bl[4];
            uint32_t pb = bAddr + p * (16 * XPB) + k * 32;
            ldsm4(bh, pb);
            ldsm4(bl, pb + DWL);
            mma16816(acc[2 * p],     ah, bh[0], bh[1]);
            mma16816(acc[2 * p],     al, bh[0], bh[1]);
            mma16816(acc[2 * p],     ah, bl[0], bl[1]);
            mma16816(acc[2 * p + 1], ah, bh[2], bh[3]);
            mma16816(acc[2 * p + 1], al, bh[2], bh[3]);
            mma16816(acc[2 * p + 1], ah, bl[2], bl[3]);
        }
    }

    // Epilogue: bias + tanh, gathered row writes.
    float br[16];
#pragma unroll
    for (int nt = 0; nt < 8; nt++) {
        br[2 * nt]     = sbias[8 * nt + 2 * tig];
        br[2 * nt + 1] = sbias[8 * nt + 2 * tig + 1];
    }
#pragma unroll
    for (int h = 0; h < 2; h++) {
        const int r = wid * 16 + h * 8 + gq;
        const int a = sp[r];
        if (a < 0) continue;
        float* orow = out + (size_t)a * D;
#pragma unroll
        for (int nt = 0; nt < 8; nt++) {
            float2 y;
            y.x = tanh_fast(acc[nt][2 * h]     + br[2 * nt]);
            y.y = tanh_fast(acc[nt][2 * h + 1] + br[2 * nt + 1]);
            *(float2*)(orow + 8 * nt + 2 * tig) = y;
        }
    }
}

// -------------------------------------------------------------- launch ----
extern "C" void kernel_launch(void* const* d_in, const int* in_sizes, int n_in,
                              void* d_out, int out_size)
{
    const float* x   = (const float*)d_in[0];
    const int*   ty  = (const int*)d_in[1];
    const float* W   = (const float*)d_in[2];
    const float* b   = (const float*)d_in[3];
    float*       out = (float*)d_out;

    const int n = in_sizes[0] / D;

    static bool attr_set = false;
    if (!attr_set) {
        cudaFuncSetAttribute(k_compute,
                             cudaFuncAttributeMaxDynamicSharedMemorySize,
                             SM_TOTAL);
        attr_set = true;
    }

    k_init<<<1, 256>>>();
    k_bucket<<<BBLK, 256>>>(ty, n);
    dim3 grid(256, MAX_TILES);
    k_compute<<<grid, 256, SM_TOTAL>>>(x, W, b, out);
}